// round 1
// baseline (speedup 1.0000x reference)
#include <cuda_runtime.h>

#define BDIM  4
#define TDIM  2048
#define CDIM  1024
#define NHEAD 16
#define HDIM  64
#define NTOK  (BDIM*TDIM)   // 8192

// ---------------- scratch (static device allocations; no cudaMalloc) ----------------
__device__ float g_Q[(size_t)NTOK * CDIM];   // [B,H,T,d]
__device__ float g_K[(size_t)NTOK * CDIM];   // [B,H,T,d]
__device__ float g_V[(size_t)NTOK * CDIM];   // [B,H,T,d]
__device__ float g_A[(size_t)NTOK * CDIM];   // attention out, [B,T,C]

// =====================================================================================
// GEMM: C[n,m] = sum_k A[n,k] * W[m,k] + bias[m]
//   A: [8192,1024] row-major, W: [1024,1024] row-major (Linear weight, so x @ W^T)
//   SPLIT=1: write head-split layout [B,H,T,d];  SPLIT=0: plain [N,M] row-major.
// 128x128 block tile, BK=16, 256 threads, 8x8 micro-tile (split halves for
// conflict-free LDS.128).
// =====================================================================================
template<int SPLIT>
__global__ __launch_bounds__(256) void gemm128(const float* __restrict__ A,
                                               const float* __restrict__ W,
                                               const float* __restrict__ bias,
                                               float* __restrict__ C) {
    __shared__ float As[16 * 132];   // k-major transposed: As[kk*132 + row]
    __shared__ float Ws[16 * 132];

    const int tid = threadIdx.x;
    const int tx = tid & 15;          // 0..15
    const int ty = tid >> 4;          // 0..15
    const int n0 = blockIdx.y << 7;
    const int m0 = blockIdx.x << 7;

    float acc[8][8];
#pragma unroll
    for (int i = 0; i < 8; i++)
#pragma unroll
        for (int j = 0; j < 8; j++) acc[i][j] = 0.0f;

    const int lc = tid & 15;   // k within k-tile
    const int lr = tid >> 4;   // row base

    for (int k0 = 0; k0 < CDIM; k0 += 16) {
#pragma unroll
        for (int i = 0; i < 8; i++) {
            const int r = lr + (i << 4);
            As[lc * 132 + r] = A[(size_t)(n0 + r) * CDIM + k0 + lc];
            Ws[lc * 132 + r] = W[(size_t)(m0 + r) * CDIM + k0 + lc];
        }
        __syncthreads();
#pragma unroll
        for (int kk = 0; kk < 16; kk++) {
            const float4 a0 = *(const float4*)&As[kk * 132 + (ty << 2)];
            const float4 a1 = *(const float4*)&As[kk * 132 + 64 + (ty << 2)];
            const float4 w0 = *(const float4*)&Ws[kk * 132 + (tx << 2)];
            const float4 w1 = *(const float4*)&Ws[kk * 132 + 64 + (tx << 2)];
            const float av[8] = {a0.x, a0.y, a0.z, a0.w, a1.x, a1.y, a1.z, a1.w};
            const float wv[8] = {w0.x, w0.y, w0.z, w0.w, w1.x, w1.y, w1.z, w1.w};
#pragma unroll
            for (int i = 0; i < 8; i++)
#pragma unroll
                for (int j = 0; j < 8; j++)
                    acc[i][j] = fmaf(av[i], wv[j], acc[i][j]);
        }
        __syncthreads();
    }

#pragma unroll
    for (int i = 0; i < 8; i++) {
        const int n = n0 + ((i < 4) ? (ty << 2) + i : 64 + (ty << 2) + i - 4);
#pragma unroll
        for (int j = 0; j < 8; j++) {
            const int m = m0 + ((j < 4) ? (tx << 2) + j : 64 + (tx << 2) + j - 4);
            const float v = acc[i][j] + bias[m];
            if (SPLIT) {
                const int bb = n >> 11;      // n / T
                const int t  = n & 2047;
                const int h  = m >> 6;       // m / HDIM
                const int dd = m & 63;
                g_dummy_noop:;
                C[(((size_t)bb * NHEAD + h) * TDIM + t) * HDIM + dd] = v;
            } else {
                C[(size_t)n * CDIM + m] = v;
            }
        }
    }
}

// =====================================================================================
// Flash attention: one block per (batch*head, 64-query tile). BLOCK_M=BLOCK_N=64.
// Q,K,V in [B,H,T,d]. Output written directly to [B,T,C] layout (head-merged).
// S stored transposed in smem: Sts[c][r] (stride 65) so softmax row-scan and the
// P.V broadcast reads are bank-conflict free.
// =====================================================================================
__global__ __launch_bounds__(256) void attn64(const float* __restrict__ Q,
                                              const float* __restrict__ K,
                                              const float* __restrict__ V,
                                              float* __restrict__ O) {
    extern __shared__ float sm[];
    float* Qts = sm;                  // [64][64] k-major: Qts[k*64 + r]
    float* Kts = sm + 4096;           // [64][64] k-major: Kts[k*64 + c]
    float* Vs  = sm + 8192;           // [64][64] row-major: Vs[c*64 + j]
    float* Sts = sm + 12288;          // [64][65]: Sts[c*65 + r]
    float* rAlpha = sm + 12288 + 4160;   // [64]
    float* rLinv  = rAlpha + 64;         // [64]

    const int tid = threadIdx.x;
    const int tx = tid & 15;
    const int ty = tid >> 4;
    const int bh = blockIdx.y;           // b*NHEAD + h
    const int q0 = blockIdx.x << 6;

    const float* Qg = Q + ((size_t)bh * TDIM + q0) * HDIM;
    const float* Kg = K + (size_t)bh * TDIM * HDIM;
    const float* Vg = V + (size_t)bh * TDIM * HDIM;

    // ---- load Q tile transposed (once) ----
    {
        const int k0 = (tid & 15) << 2;
#pragma unroll
        for (int it = 0; it < 4; it++) {
            const int r = (tid >> 4) + (it << 4);
            const float4 q4 = *(const float4*)&Qg[(size_t)r * HDIM + k0];
            Qts[(k0 + 0) * 64 + r] = q4.x;
            Qts[(k0 + 1) * 64 + r] = q4.y;
            Qts[(k0 + 2) * 64 + r] = q4.z;
            Qts[(k0 + 3) * 64 + r] = q4.w;
        }
    }

    float o[4][4];
#pragma unroll
    for (int i = 0; i < 4; i++)
#pragma unroll
        for (int j = 0; j < 4; j++) o[i][j] = 0.0f;

    float m_r = -1e30f;   // only meaningful for tid < 64
    float l_r = 0.0f;

    for (int kt = 0; kt < TDIM / 64; kt++) {
        __syncthreads();   // previous iteration done reading Vs/Sts
        // ---- load K tile transposed + V tile ----
        {
            const int k0 = (tid & 15) << 2;
            const float* Kt = Kg + (size_t)(kt << 6) * HDIM;
#pragma unroll
            for (int it = 0; it < 4; it++) {
                const int c = (tid >> 4) + (it << 4);
                const float4 k4 = *(const float4*)&Kt[(size_t)c * HDIM + k0];
                Kts[(k0 + 0) * 64 + c] = k4.x;
                Kts[(k0 + 1) * 64 + c] = k4.y;
                Kts[(k0 + 2) * 64 + c] = k4.z;
                Kts[(k0 + 3) * 64 + c] = k4.w;
            }
            const float* Vt = Vg + (size_t)(kt << 6) * HDIM;
#pragma unroll
            for (int it = 0; it < 4; it++) {
                const int idx = (tid + (it << 8)) << 2;   // 0..4092
                *(float4*)&Vs[idx] = *(const float4*)&Vt[idx];
            }
        }
        __syncthreads();

        // ---- S = (K . Q^T) * scale, stored Sts[c][r] ----
        {
            float s[4][4];
#pragma unroll
            for (int i = 0; i < 4; i++)
#pragma unroll
                for (int j = 0; j < 4; j++) s[i][j] = 0.0f;
#pragma unroll 8
            for (int k = 0; k < 64; k++) {
                const float4 kv = *(const float4*)&Kts[k * 64 + (ty << 2)];
                const float4 qv = *(const float4*)&Qts[k * 64 + (tx << 2)];
                const float kc[4] = {kv.x, kv.y, kv.z, kv.w};
                const float qr[4] = {qv.x, qv.y, qv.z, qv.w};
#pragma unroll
                for (int i = 0; i < 4; i++)
#pragma unroll
                    for (int j = 0; j < 4; j++)
                        s[i][j] = fmaf(kc[i], qr[j], s[i][j]);
            }
#pragma unroll
            for (int i = 0; i < 4; i++)
#pragma unroll
                for (int j = 0; j < 4; j++)
                    Sts[((ty << 2) + i) * 65 + (tx << 2) + j] = s[i][j] * 0.125f;
        }
        __syncthreads();

        // ---- online softmax (one thread per query row) ----
        if (tid < 64) {
            const int r = tid;
            float mx = m_r;
#pragma unroll 8
            for (int c = 0; c < 64; c++) mx = fmaxf(mx, Sts[c * 65 + r]);
            const float alpha = __expf(m_r - mx);
            float sum = 0.0f;
#pragma unroll 8
            for (int c = 0; c < 64; c++) {
                const float p = __expf(Sts[c * 65 + r] - mx);
                Sts[c * 65 + r] = p;
                sum += p;
            }
            l_r = l_r * alpha + sum;
            m_r = mx;
            rAlpha[r] = alpha;
        }
        __syncthreads();

        // ---- O = O*alpha + P . V ----
        {
            float al[4];
#pragma unroll
            for (int i = 0; i < 4; i++) al[i] = rAlpha[(ty << 2) + i];
#pragma unroll
            for (int i = 0; i < 4; i++)
#pragma unroll
                for (int j = 0; j < 4; j++) o[i][j] *= al[i];
#pragma unroll 8
            for (int c = 0; c < 64; c++) {
                const float4 vv = *(const float4*)&Vs[c * 64 + (tx << 2)];
                const float vj[4] = {vv.x, vv.y, vv.z, vv.w};
                float p[4];
#pragma unroll
                for (int i = 0; i < 4; i++) p[i] = Sts[c * 65 + (ty << 2) + i];
#pragma unroll
                for (int i = 0; i < 4; i++)
#pragma unroll
                    for (int j = 0; j < 4; j++)
                        o[i][j] = fmaf(p[i], vj[j], o[i][j]);
            }
        }
    }

    __syncthreads();
    if (tid < 64) rLinv[tid] = 1.0f / l_r;
    __syncthreads();

    // ---- write out to [B, T, C] with head-merged columns ----
    {
        const int b = bh >> 4;
        const int h = bh & 15;
#pragma unroll
        for (int i = 0; i < 4; i++) {
            const float inv = rLinv[(ty << 2) + i];
            float4 ov;
            ov.x = o[i][0] * inv;
            ov.y = o[i][1] * inv;
            ov.z = o[i][2] * inv;
            ov.w = o[i][3] * inv;
            const size_t n = (size_t)b * TDIM + q0 + (ty << 2) + i;
            *(float4*)&O[n * CDIM + h * HDIM + (tx << 2)] = ov;
        }
    }
}

// =====================================================================================
extern "C" void kernel_launch(void* const* d_in, const int* in_sizes, int n_in,
                              void* d_out, int out_size) {
    const float* x  = (const float*)d_in[0];
    const float* Wq = (const float*)d_in[1];
    const float* bq = (const float*)d_in[2];
    const float* Wk = (const float*)d_in[3];
    const float* bk = (const float*)d_in[4];
    const float* Wv = (const float*)d_in[5];
    const float* bv = (const float*)d_in[6];
    const float* Wp = (const float*)d_in[7];
    const float* bp = (const float*)d_in[8];
    float* out = (float*)d_out;

    float *Qp, *Kp, *Vp, *Ap;
    cudaGetSymbolAddress((void**)&Qp, g_Q);
    cudaGetSymbolAddress((void**)&Kp, g_K);
    cudaGetSymbolAddress((void**)&Vp, g_V);
    cudaGetSymbolAddress((void**)&Ap, g_A);

    const dim3 gg(CDIM / 128, NTOK / 128);   // (8, 64)

    gemm128<1><<<gg, 256>>>(x, Wq, bq, Qp);
    gemm128<1><<<gg, 256>>>(x, Wk, bk, Kp);
    gemm128<1><<<gg, 256>>>(x, Wv, bv, Vp);

    const int smem_bytes = (4096 * 3 + 64 * 65 + 128) * (int)sizeof(float);  // 66816 B
    cudaFuncSetAttribute(attn64, cudaFuncAttributeMaxDynamicSharedMemorySize, smem_bytes);
    const dim3 ga(TDIM / 64, BDIM * NHEAD);  // (32, 64)
    attn64<<<ga, 256, smem_bytes>>>(Qp, Kp, Vp, Ap);

    gemm128<0><<<gg, 256>>>(Ap, Wp, bp, out);
}